// round 16
// baseline (speedup 1.0000x reference)
#include <cuda_runtime.h>
#include <cuda_fp16.h>
#include <mma.h>
#include <cstdint>

using namespace nvcuda;

// ---------------- problem constants ----------------
#define BB 16
#define EE 8
#define CC 1024
#define DD 512
#define FF 2048

// ---------------- tiling (round-4 proven config) ----------------
#define BM 128
#define BN 128
#define BK 64
#define KS 72                          // smem row stride in halfs (144B)
#define A_ROWS 128
#define B_ROWS 128
#define STAGE_ELEMS ((A_ROWS + B_ROWS) * KS)
#define STAGE_BYTES (STAGE_ELEMS * 2)  // 36864
#define NSTAGE 3
#define SMEM_TOTAL (NSTAGE * STAGE_BYTES)   // 110592 -> 2 CTAs/SM
#define EPI_LD 132                     // f32 stage / bias-tile stride

// ---------------- scratch (device globals; no allocs) ----------------
__device__ __half g_Xh [(size_t)BB * EE * CC * DD];      // X  fp16
__device__ __half g_W1t[(size_t)EE * FF * DD];           // W1^T [e][n=F][k=D]
__device__ __half g_W2t[(size_t)EE * DD * FF];           // W2^T [e][n=D][k=F]
__device__ __half g_Hh [(size_t)BB * EE * CC * FF];      // H  fp16

// ---------------- PTX helpers ----------------
__device__ __forceinline__ uint32_t smem_u32(const void* p) {
    uint32_t a;
    asm("{ .reg .u64 t; cvta.to.shared.u64 t, %1; cvt.u32.u64 %0, t; }" : "=r"(a) : "l"(p));
    return a;
}
#define CP_ASYNC16(dst, src) \
    asm volatile("cp.async.cg.shared.global [%0], [%1], 16;" :: "r"(dst), "l"(src) : "memory")
#define CP_COMMIT()  asm volatile("cp.async.commit_group;" ::: "memory")
#define CP_WAIT1()   asm volatile("cp.async.wait_group 1;" ::: "memory")

// ---------------- math helpers ----------------
__device__ __forceinline__ float gelu_fast(float x) {
    float u = 0.7978845608028654f * fmaf(0.044715f * x, x * x, x);
    float y = 2.8853900817779268f * u;     // 2u / ln2
    float z;
    asm("ex2.approx.f32 %0, %1;" : "=f"(z) : "f"(y));
    float t = 1.0f - __fdividef(2.0f, z + 1.0f);
    return 0.5f * x * (1.0f + t);
}

// ---------------- prepass: fp32 -> fp16 (coalesced) ----------------
__global__ void to_fp16(const float* __restrict__ src, __half* __restrict__ dst, size_t n4) {
    size_t i = blockIdx.x * (size_t)blockDim.x + threadIdx.x;
    if (i >= n4) return;
    float4 v = reinterpret_cast<const float4*>(src)[i];
    __half2 h0 = __floats2half2_rn(v.x, v.y);
    __half2 h1 = __floats2half2_rn(v.z, v.w);
    uint2 u;
    u.x = *reinterpret_cast<unsigned*>(&h0);
    u.y = *reinterpret_cast<unsigned*>(&h1);
    reinterpret_cast<uint2*>(dst)[i] = u;
}

// ---------------- prepass: tiled transpose  w[e][K][N] -> t[e][N][K] fp16 ----------------
__global__ void transpose_fp16(const float* __restrict__ w, __half* __restrict__ t,
                               int K, int N) {
    __shared__ float tile[32][33];
    const int e = blockIdx.z;
    const int k0 = blockIdx.y * 32;
    const int n0 = blockIdx.x * 32;
    const float* we = w + (size_t)e * K * N;
#pragma unroll
    for (int i = 0; i < 4; i++) {
        int k = k0 + threadIdx.y + i * 8;
        tile[threadIdx.y + i * 8][threadIdx.x] = we[(size_t)k * N + n0 + threadIdx.x];
    }
    __syncthreads();
    __half* te = t + (size_t)e * N * K;
#pragma unroll
    for (int i = 0; i < 4; i++) {
        int n = n0 + threadIdx.y + i * 8;
        te[(size_t)n * K + k0 + threadIdx.x] = __float2half_rn(tile[threadIdx.x][threadIdx.y + i * 8]);
    }
}

// ---------------- main grouped GEMM ----------------
// Both modes: bias folded into accumulator init (verified r14/r15).
// mode0 (GEMM1): staged f32 epilogue (r14 shape), gelu only (no bias reload) -> Oh fp16
// mode1 (GEMM2): direct store_matrix_sync -> outF (r14 proven)
__global__ void __launch_bounds__(256, 2)
moe_gemm(const __half* __restrict__ Ah, const __half* __restrict__ Bh,
         const float* __restrict__ bias,
         float* __restrict__ outF, __half* __restrict__ Oh,
         int K, int Ntot, int mode)
{
    extern __shared__ char smc[];
    const uint32_t sbase = smem_u32(smc);
    const int tid = threadIdx.x;
    const int wid = tid >> 5;

    const int g = blockIdx.z;
    const int e = g & (EE - 1);
    const int mBase = blockIdx.y * BM;
    const int nBase = blockIdx.x * BN;

    const __half* aP = Ah + (size_t)g * CC * K + (size_t)mBase * K;
    const __half* bP = Bh + (size_t)e * Ntot * K + (size_t)nBase * K;

    const int KT = K / BK;

    auto loadStage = [&](int kt) {
        const int k0 = kt * BK;
        const uint32_t s = sbase + (uint32_t)((kt % NSTAGE) * STAGE_BYTES);
#pragma unroll
        for (int i = 0; i < 4; i++) {
            int idx = tid + i * 256;
            int row = idx >> 3, q = idx & 7;
            uint32_t d = s + (uint32_t)(row * (KS * 2) + q * 16);
            size_t go = (size_t)row * K + k0 + q * 8;
            CP_ASYNC16(d, aP + go);
            CP_ASYNC16(d + A_ROWS * KS * 2, bP + go);
        }
    };

    const int wm = (wid & 1) * 64;
    const int wn = (wid >> 1) * 32;

    // ---- bias-in-accumulator init (both modes; mechanism verified r14/r15) ----
    wmma::fragment<wmma::accumulator, 16, 16, 16, float> acc[4][2];
    {
        float* bt = reinterpret_cast<float*>(smc);
#pragma unroll
        for (int i = 0; i < 8; i++) {
            int idx = tid + i * 256;             // 0..2047
            int rw = idx >> 7;                   // 0..15
            int cl = idx & 127;                  // 0..127
            bt[rw * EPI_LD + cl] = bias[nBase + cl];
        }
        __syncthreads();
#pragma unroll
        for (int mi = 0; mi < 4; mi++)
#pragma unroll
            for (int ni = 0; ni < 2; ni++)
                wmma::load_matrix_sync(acc[mi][ni], bt + wn + ni * 16, EPI_LD,
                                       wmma::mem_row_major);
        __syncthreads();   // all reads of bt done before cp.async overwrites slots
    }

    loadStage(0); CP_COMMIT();
    loadStage(1); CP_COMMIT();

    for (int kt = 0; kt < KT; kt++) {
        CP_WAIT1();
        __syncthreads();
        if (kt + 2 < KT) loadStage(kt + 2);
        CP_COMMIT();

        const __half* sA = (const __half*)(smc + (kt % NSTAGE) * STAGE_BYTES);
        const __half* sB = sA + A_ROWS * KS;

#pragma unroll
        for (int ks = 0; ks < 4; ks++) {
            wmma::fragment<wmma::matrix_a, 16, 16, 16, __half, wmma::row_major> fa[4];
            wmma::fragment<wmma::matrix_b, 16, 16, 16, __half, wmma::col_major> fb[2];
#pragma unroll
            for (int mi = 0; mi < 4; mi++)
                wmma::load_matrix_sync(fa[mi], sA + (wm + mi * 16) * KS + ks * 16, KS);
#pragma unroll
            for (int ni = 0; ni < 2; ni++)
                wmma::load_matrix_sync(fb[ni], sB + (wn + ni * 16) * KS + ks * 16, KS);
#pragma unroll
            for (int mi = 0; mi < 4; mi++)
#pragma unroll
                for (int ni = 0; ni < 2; ni++)
                    wmma::mma_sync(acc[mi][ni], fa[mi], fb[ni], acc[mi][ni]);
        }
    }

    if (mode == 1) {
        // GEMM2: bias already in acc; store straight to GMEM (64B row segments)
#pragma unroll
        for (int mi = 0; mi < 4; mi++)
#pragma unroll
            for (int ni = 0; ni < 2; ni++) {
                size_t off = (size_t)g * CC * Ntot
                           + (size_t)(mBase + wm + mi * 16) * Ntot + nBase + wn + ni * 16;
                wmma::store_matrix_sync(outF + off, acc[mi][ni], Ntot, wmma::mem_row_major);
            }
        return;
    }

    // ---- GEMM1 epilogue (r14 staged shape, bias already in acc): gelu + fp16 pack ----
    __syncthreads();
    float* stage = reinterpret_cast<float*>(smc);
#pragma unroll
    for (int mi = 0; mi < 4; mi++)
#pragma unroll
        for (int ni = 0; ni < 2; ni++)
            wmma::store_matrix_sync(&stage[(wm + mi * 16) * EPI_LD + wn + ni * 16],
                                    acc[mi][ni], EPI_LD, wmma::mem_row_major);
    __syncthreads();

#pragma unroll
    for (int i = 0; i < 16; i++) {
        int idx = tid + i * 256;
        int row = idx >> 5;
        int c4 = idx & 31;
        float4 v = *reinterpret_cast<float4*>(&stage[row * EPI_LD + c4 * 4]);
        size_t off = (size_t)g * CC * Ntot + (size_t)(mBase + row) * Ntot + nBase + c4 * 4;
        __half2 h0 = __floats2half2_rn(gelu_fast(v.x), gelu_fast(v.y));
        __half2 h1 = __floats2half2_rn(gelu_fast(v.z), gelu_fast(v.w));
        uint2 u;
        u.x = *reinterpret_cast<unsigned*>(&h0);
        u.y = *reinterpret_cast<unsigned*>(&h1);
        *reinterpret_cast<uint2*>(Oh + off) = u;
    }
}

// ---------------- host launcher with fork/join stream overlap (round-10 proven) ----------------
static cudaStream_t g_s1 = nullptr, g_s2 = nullptr;
static cudaEvent_t g_e0, g_e1, g_e2;
static bool g_init = false;

extern "C" void kernel_launch(void* const* d_in, const int* in_sizes, int n_in,
                              void* d_out, int out_size) {
    const float* inputs = (const float*)d_in[0];
    const float* w1     = (const float*)d_in[1];
    const float* b1     = (const float*)d_in[2];
    const float* w2     = (const float*)d_in[3];
    const float* b2     = (const float*)d_in[4];
    float*       out    = (float*)d_out;

    void *xh, *w1t, *w2t, *hh;
    cudaGetSymbolAddress(&xh, g_Xh);
    cudaGetSymbolAddress(&w1t, g_W1t);
    cudaGetSymbolAddress(&w2t, g_W2t);
    cudaGetSymbolAddress(&hh, g_Hh);

    if (!g_init) {
        cudaStreamCreateWithFlags(&g_s1, cudaStreamNonBlocking);
        cudaStreamCreateWithFlags(&g_s2, cudaStreamNonBlocking);
        cudaEventCreateWithFlags(&g_e0, cudaEventDisableTiming);
        cudaEventCreateWithFlags(&g_e1, cudaEventDisableTiming);
        cudaEventCreateWithFlags(&g_e2, cudaEventDisableTiming);
        cudaFuncSetAttribute(moe_gemm, cudaFuncAttributeMaxDynamicSharedMemorySize, SMEM_TOTAL);
        g_init = true;
    }

    // fork: side streams wait on the main stream's current point
    cudaEventRecord(g_e0, 0);
    cudaStreamWaitEvent(g_s1, g_e0, 0);
    cudaStreamWaitEvent(g_s2, g_e0, 0);

    // main stream: X convert (GEMM1's critical input)
    {
        size_t n4 = (size_t)BB * EE * CC * DD / 4;
        to_fp16<<<(unsigned)((n4 + 255) / 256), 256, 0, 0>>>(inputs, (__half*)xh, n4);
    }
    // s1: W1 transpose (needed before GEMM1)
    {
        dim3 blk(32, 8);
        dim3 gr(FF / 32, DD / 32, EE);
        transpose_fp16<<<gr, blk, 0, g_s1>>>(w1, (__half*)w1t, DD, FF);
        cudaEventRecord(g_e1, g_s1);
    }
    // s2: W2 transpose (only needed before GEMM2 -> hidden under GEMM1)
    {
        dim3 blk(32, 8);
        dim3 gr(DD / 32, FF / 32, EE);
        transpose_fp16<<<gr, blk, 0, g_s2>>>(w2, (__half*)w2t, FF, DD);
        cudaEventRecord(g_e2, g_s2);
    }

    // join W1t, then GEMM1: H = gelu(X @ W1^T + b1)
    cudaStreamWaitEvent(0, g_e1, 0);
    {
        dim3 grid(FF / BN, CC / BM, BB * EE);
        moe_gemm<<<grid, 256, SMEM_TOTAL, 0>>>(
            (const __half*)xh, (const __half*)w1t, b1,
            nullptr, (__half*)hh, DD, FF, 0);
    }

    // join W2t, then GEMM2: Y = H @ W2^T + b2 (bias-in-acc, direct store)
    cudaStreamWaitEvent(0, g_e2, 0);
    {
        dim3 grid(DD / BN, CC / BM, BB * EE);
        moe_gemm<<<grid, 256, SMEM_TOTAL, 0>>>(
            (const __half*)hh, (const __half*)w2t, b2,
            out, nullptr, FF, DD, 1);
    }
}

// round 17
// speedup vs baseline: 1.0459x; 1.0459x over previous
#include <cuda_runtime.h>
#include <cuda_fp16.h>
#include <mma.h>
#include <cstdint>

using namespace nvcuda;

// ---------------- problem constants ----------------
#define BB 16
#define EE 8
#define CC 1024
#define DD 512
#define FF 2048

// ---------------- tiling (round-4 proven config) ----------------
#define BM 128
#define BN 128
#define BK 64
#define KS 72                          // smem row stride in halfs (144B)
#define A_ROWS 128
#define B_ROWS 128
#define STAGE_ELEMS ((A_ROWS + B_ROWS) * KS)
#define STAGE_BYTES (STAGE_ELEMS * 2)  // 36864
#define NSTAGE 3
#define SMEM_TOTAL (NSTAGE * STAGE_BYTES)   // 110592 -> 2 CTAs/SM
#define EPI_LD 132

// ---------------- scratch (device globals; no allocs) ----------------
__device__ __half g_Xh [(size_t)BB * EE * CC * DD];      // X  fp16
__device__ __half g_W1t[(size_t)EE * FF * DD];           // W1^T [e][n=F][k=D]
__device__ __half g_W2t[(size_t)EE * DD * FF];           // W2^T [e][n=D][k=F]
__device__ __half g_Hh [(size_t)BB * EE * CC * FF];      // H  fp16

// ---------------- PTX helpers ----------------
__device__ __forceinline__ uint32_t smem_u32(const void* p) {
    uint32_t a;
    asm("{ .reg .u64 t; cvta.to.shared.u64 t, %1; cvt.u32.u64 %0, t; }" : "=r"(a) : "l"(p));
    return a;
}
#define CP_ASYNC16(dst, src) \
    asm volatile("cp.async.cg.shared.global [%0], [%1], 16;" :: "r"(dst), "l"(src) : "memory")
#define CP_COMMIT()  asm volatile("cp.async.commit_group;" ::: "memory")
#define CP_WAIT1()   asm volatile("cp.async.wait_group 1;" ::: "memory")

// ---------------- math helpers ----------------
__device__ __forceinline__ float gelu_fast(float x) {
    float u = 0.7978845608028654f * fmaf(0.044715f * x, x * x, x);
    float y = 2.8853900817779268f * u;     // 2u / ln2
    float z;
    asm("ex2.approx.f32 %0, %1;" : "=f"(z) : "f"(y));
    float t = 1.0f - __fdividef(2.0f, z + 1.0f);
    return 0.5f * x * (1.0f + t);
}

// ---------------- prepass: fp32 -> fp16 (coalesced) ----------------
__global__ void to_fp16(const float* __restrict__ src, __half* __restrict__ dst, size_t n4) {
    size_t i = blockIdx.x * (size_t)blockDim.x + threadIdx.x;
    if (i >= n4) return;
    float4 v = reinterpret_cast<const float4*>(src)[i];
    __half2 h0 = __floats2half2_rn(v.x, v.y);
    __half2 h1 = __floats2half2_rn(v.z, v.w);
    uint2 u;
    u.x = *reinterpret_cast<unsigned*>(&h0);
    u.y = *reinterpret_cast<unsigned*>(&h1);
    reinterpret_cast<uint2*>(dst)[i] = u;
}

// ---------------- prepass: tiled transpose  w[e][K][N] -> t[e][N][K] fp16 ----------------
__global__ void transpose_fp16(const float* __restrict__ w, __half* __restrict__ t,
                               int K, int N) {
    __shared__ float tile[32][33];
    const int e = blockIdx.z;
    const int k0 = blockIdx.y * 32;
    const int n0 = blockIdx.x * 32;
    const float* we = w + (size_t)e * K * N;
#pragma unroll
    for (int i = 0; i < 4; i++) {
        int k = k0 + threadIdx.y + i * 8;
        tile[threadIdx.y + i * 8][threadIdx.x] = we[(size_t)k * N + n0 + threadIdx.x];
    }
    __syncthreads();
    __half* te = t + (size_t)e * N * K;
#pragma unroll
    for (int i = 0; i < 4; i++) {
        int n = n0 + threadIdx.y + i * 8;
        te[(size_t)n * K + k0 + threadIdx.x] = __float2half_rn(tile[threadIdx.x][threadIdx.y + i * 8]);
    }
}

// ---------------- main grouped GEMM (round-14 best) ----------------
// mode0 (GEMM1): acc=0 init, staged f32 epilogue with bias+gelu -> Oh fp16
// mode1 (GEMM2): bias folded into acc init, DIRECT store_matrix_sync -> outF
__global__ void __launch_bounds__(256, 2)
moe_gemm(const __half* __restrict__ Ah, const __half* __restrict__ Bh,
         const float* __restrict__ bias,
         float* __restrict__ outF, __half* __restrict__ Oh,
         int K, int Ntot, int mode)
{
    extern __shared__ char smc[];
    const uint32_t sbase = smem_u32(smc);
    const int tid = threadIdx.x;
    const int wid = tid >> 5;

    const int g = blockIdx.z;
    const int e = g & (EE - 1);
    const int mBase = blockIdx.y * BM;
    const int nBase = blockIdx.x * BN;

    const __half* aP = Ah + (size_t)g * CC * K + (size_t)mBase * K;
    const __half* bP = Bh + (size_t)e * Ntot * K + (size_t)nBase * K;

    const int KT = K / BK;

    auto loadStage = [&](int kt) {
        const int k0 = kt * BK;
        const uint32_t s = sbase + (uint32_t)((kt % NSTAGE) * STAGE_BYTES);
#pragma unroll
        for (int i = 0; i < 4; i++) {
            int idx = tid + i * 256;
            int row = idx >> 3, q = idx & 7;
            uint32_t d = s + (uint32_t)(row * (KS * 2) + q * 16);
            size_t go = (size_t)row * K + k0 + q * 8;
            CP_ASYNC16(d, aP + go);
            CP_ASYNC16(d + A_ROWS * KS * 2, bP + go);
        }
    };

    const int wm = (wid & 1) * 64;
    const int wn = (wid >> 1) * 32;

    wmma::fragment<wmma::accumulator, 16, 16, 16, float> acc[4][2];
    if (mode == 1) {
        // bias-in-accumulator: build 16-row replicated bias tile in smem, load acc from it.
        float* bt = reinterpret_cast<float*>(smc);
#pragma unroll
        for (int i = 0; i < 8; i++) {
            int idx = tid + i * 256;             // 0..2047
            int rw = idx >> 7;                   // 0..15
            int cl = idx & 127;                  // 0..127
            bt[rw * EPI_LD + cl] = bias[nBase + cl];
        }
        __syncthreads();
#pragma unroll
        for (int mi = 0; mi < 4; mi++)
#pragma unroll
            for (int ni = 0; ni < 2; ni++)
                wmma::load_matrix_sync(acc[mi][ni], bt + wn + ni * 16, EPI_LD,
                                       wmma::mem_row_major);
        __syncthreads();   // all reads of bt done before cp.async overwrites slots
    } else {
#pragma unroll
        for (int mi = 0; mi < 4; mi++)
#pragma unroll
            for (int ni = 0; ni < 2; ni++)
                wmma::fill_fragment(acc[mi][ni], 0.0f);
    }

    loadStage(0); CP_COMMIT();
    loadStage(1); CP_COMMIT();

    for (int kt = 0; kt < KT; kt++) {
        CP_WAIT1();
        __syncthreads();
        if (kt + 2 < KT) loadStage(kt + 2);
        CP_COMMIT();

        const __half* sA = (const __half*)(smc + (kt % NSTAGE) * STAGE_BYTES);
        const __half* sB = sA + A_ROWS * KS;

#pragma unroll
        for (int ks = 0; ks < 4; ks++) {
            wmma::fragment<wmma::matrix_a, 16, 16, 16, __half, wmma::row_major> fa[4];
            wmma::fragment<wmma::matrix_b, 16, 16, 16, __half, wmma::col_major> fb[2];
#pragma unroll
            for (int mi = 0; mi < 4; mi++)
                wmma::load_matrix_sync(fa[mi], sA + (wm + mi * 16) * KS + ks * 16, KS);
#pragma unroll
            for (int ni = 0; ni < 2; ni++)
                wmma::load_matrix_sync(fb[ni], sB + (wn + ni * 16) * KS + ks * 16, KS);
#pragma unroll
            for (int mi = 0; mi < 4; mi++)
#pragma unroll
                for (int ni = 0; ni < 2; ni++)
                    wmma::mma_sync(acc[mi][ni], fa[mi], fb[ni], acc[mi][ni]);
        }
    }

    if (mode == 1) {
        // direct epilogue: bias already in acc; store straight to GMEM (64B row segments)
#pragma unroll
        for (int mi = 0; mi < 4; mi++)
#pragma unroll
            for (int ni = 0; ni < 2; ni++) {
                size_t off = (size_t)g * CC * Ntot
                           + (size_t)(mBase + wm + mi * 16) * Ntot + nBase + wn + ni * 16;
                wmma::store_matrix_sync(outF + off, acc[mi][ni], Ntot, wmma::mem_row_major);
            }
        return;
    }

    // ---- mode0 epilogue: stage f32, bias+gelu, fp16 pack (r4/r13 proven shape) ----
    __syncthreads();
    float* stage = reinterpret_cast<float*>(smc);
#pragma unroll
    for (int mi = 0; mi < 4; mi++)
#pragma unroll
        for (int ni = 0; ni < 2; ni++)
            wmma::store_matrix_sync(&stage[(wm + mi * 16) * EPI_LD + wn + ni * 16],
                                    acc[mi][ni], EPI_LD, wmma::mem_row_major);
    __syncthreads();

#pragma unroll
    for (int i = 0; i < 16; i++) {
        int idx = tid + i * 256;
        int row = idx >> 5;
        int c4 = idx & 31;
        float4 v = *reinterpret_cast<float4*>(&stage[row * EPI_LD + c4 * 4]);
        int n = nBase + c4 * 4;
        v.x += bias[n + 0]; v.y += bias[n + 1]; v.z += bias[n + 2]; v.w += bias[n + 3];
        size_t off = (size_t)g * CC * Ntot + (size_t)(mBase + row) * Ntot + n;
        __half2 h0 = __floats2half2_rn(gelu_fast(v.x), gelu_fast(v.y));
        __half2 h1 = __floats2half2_rn(gelu_fast(v.z), gelu_fast(v.w));
        uint2 u;
        u.x = *reinterpret_cast<unsigned*>(&h0);
        u.y = *reinterpret_cast<unsigned*>(&h1);
        *reinterpret_cast<uint2*>(Oh + off) = u;
    }
}

// ---------------- host launcher with fork/join stream overlap (round-10 proven) ----------------
static cudaStream_t g_s1 = nullptr, g_s2 = nullptr;
static cudaEvent_t g_e0, g_e1, g_e2;
static bool g_init = false;

extern "C" void kernel_launch(void* const* d_in, const int* in_sizes, int n_in,
                              void* d_out, int out_size) {
    const float* inputs = (const float*)d_in[0];
    const float* w1     = (const float*)d_in[1];
    const float* b1     = (const float*)d_in[2];
    const float* w2     = (const float*)d_in[3];
    const float* b2     = (const float*)d_in[4];
    float*       out    = (float*)d_out;

    void *xh, *w1t, *w2t, *hh;
    cudaGetSymbolAddress(&xh, g_Xh);
    cudaGetSymbolAddress(&w1t, g_W1t);
    cudaGetSymbolAddress(&w2t, g_W2t);
    cudaGetSymbolAddress(&hh, g_Hh);

    if (!g_init) {
        cudaStreamCreateWithFlags(&g_s1, cudaStreamNonBlocking);
        cudaStreamCreateWithFlags(&g_s2, cudaStreamNonBlocking);
        cudaEventCreateWithFlags(&g_e0, cudaEventDisableTiming);
        cudaEventCreateWithFlags(&g_e1, cudaEventDisableTiming);
        cudaEventCreateWithFlags(&g_e2, cudaEventDisableTiming);
        cudaFuncSetAttribute(moe_gemm, cudaFuncAttributeMaxDynamicSharedMemorySize, SMEM_TOTAL);
        g_init = true;
    }

    // fork: side streams wait on the main stream's current point
    cudaEventRecord(g_e0, 0);
    cudaStreamWaitEvent(g_s1, g_e0, 0);
    cudaStreamWaitEvent(g_s2, g_e0, 0);

    // main stream: X convert (GEMM1's critical input)
    {
        size_t n4 = (size_t)BB * EE * CC * DD / 4;
        to_fp16<<<(unsigned)((n4 + 255) / 256), 256, 0, 0>>>(inputs, (__half*)xh, n4);
    }
    // s1: W1 transpose (needed before GEMM1)
    {
        dim3 blk(32, 8);
        dim3 gr(FF / 32, DD / 32, EE);
        transpose_fp16<<<gr, blk, 0, g_s1>>>(w1, (__half*)w1t, DD, FF);
        cudaEventRecord(g_e1, g_s1);
    }
    // s2: W2 transpose (only needed before GEMM2 -> hidden under GEMM1)
    {
        dim3 blk(32, 8);
        dim3 gr(DD / 32, FF / 32, EE);
        transpose_fp16<<<gr, blk, 0, g_s2>>>(w2, (__half*)w2t, FF, DD);
        cudaEventRecord(g_e2, g_s2);
    }

    // join W1t, then GEMM1: H = gelu(X @ W1^T + b1)
    cudaStreamWaitEvent(0, g_e1, 0);
    {
        dim3 grid(FF / BN, CC / BM, BB * EE);
        moe_gemm<<<grid, 256, SMEM_TOTAL, 0>>>(
            (const __half*)xh, (const __half*)w1t, b1,
            nullptr, (__half*)hh, DD, FF, 0);
    }

    // join W2t, then GEMM2: Y = H @ W2^T + b2 (bias-in-acc, direct store)
    cudaStreamWaitEvent(0, g_e2, 0);
    {
        dim3 grid(DD / BN, CC / BM, BB * EE);
        moe_gemm<<<grid, 256, SMEM_TOTAL, 0>>>(
            (const __half*)hh, (const __half*)w2t, b2,
            out, nullptr, FF, DD, 1);
    }
}